// round 3
// baseline (speedup 1.0000x reference)
#include <cuda_runtime.h>

#define CC 64
#define NPIX (512*512)
#define NL 8
#define SUBT 128
#define PITCH 68
#define NTILE (NPIX/SUBT)
#define APT 256
#define NATILE (NPIX/APT)
#define TSTRIDE 4100
#define NS_IT 7

// ---------------- global scratch (no allocations allowed) ----------------
__device__ float        g_S1[2][NL][CC];
__device__ float        g_S2[2][NL][CC*CC];
__device__ unsigned int g_cnt[2][NL];
__device__ float        g_WC[2][NL][CC*CC];   // [0]=Wh=cov_c^{-1/2}, [1]=Co=cov_s^{1/2}
__device__ float        g_mu[2][NL][CC];
__device__ float        g_T[NL][CC*CC];
__device__ float        g_beta[NL][CC];
__device__ int          g_valid[NL];

__global__ void zero_kernel() {
    int i = blockIdx.x * blockDim.x + threadIdx.x;
    int st = gridDim.x * blockDim.x;
    float* p2 = &g_S2[0][0][0];
    for (int k = i; k < 2*NL*CC*CC; k += st) p2[k] = 0.f;
    float* p1 = &g_S1[0][0][0];
    for (int k = i; k < 2*NL*CC; k += st) p1[k] = 0.f;
    if (i < 2*NL) (&g_cnt[0][0])[i] = 0u;
}

// ================= stats: per-label count, S1, S2 = X X^T =================
__global__ __launch_bounds__(256, 1)
void stats_kernel(const float* __restrict__ cf, const float* __restrict__ sf,
                  const int* __restrict__ cs, const int* __restrict__ ss) {
    int which = blockIdx.y;
    const float* feat = which ? sf : cf;
    const int*   seg  = which ? ss : cs;

    __shared__ float xt[SUBT*PITCH];
    __shared__ unsigned short lst[NL][SUBT];
    __shared__ int cnt[NL];
    __shared__ float s1[NL][CC];
    __shared__ unsigned int gcnt[NL];

    int tid = threadIdx.x;
    for (int k = tid; k < NL*CC; k += 256) (&s1[0][0])[k] = 0.f;
    if (tid < NL) gcnt[tid] = 0u;

    int rr = tid >> 4, cr = tid & 15;
    float acc[NL][16];
    #pragma unroll
    for (int l = 0; l < NL; l++)
        #pragma unroll
        for (int j = 0; j < 16; j++) acc[l][j] = 0.f;

    for (int t = blockIdx.x; t < NTILE; t += gridDim.x) {
        int base = t * SUBT;
        __syncthreads();                       // prior subtile fully consumed
        if (tid < NL) cnt[tid] = 0;
        __syncthreads();
        if (tid < SUBT) {
            int lab = seg[base + tid] & 7;
            int pos = atomicAdd(&cnt[lab], 1);
            lst[lab][pos] = (unsigned short)tid;
        }
        #pragma unroll 4
        for (int k = tid; k < SUBT*CC; k += 256) {
            int c = k >> 7, p = k & (SUBT-1);
            xt[p*PITCH + c] = feat[c*NPIX + base + p];
        }
        __syncthreads();
        if (tid < NL) gcnt[tid] += (unsigned int)cnt[tid];

        // S1: 4 threads per channel strided over each label list
        {
            int c = tid & 63, kk = tid >> 6;
            #pragma unroll
            for (int l = 0; l < NL; l++) {
                int n = cnt[l];
                float a = 0.f;
                for (int k = kk; k < n; k += 4) a += xt[(int)lst[l][k]*PITCH + c];
                atomicAdd(&s1[l][c], a);
            }
        }
        // S2 rank-n updates, thread owns 4x4 tile of 64x64 per label
        #pragma unroll
        for (int l = 0; l < NL; l++) {
            int n = cnt[l];
            for (int k = 0; k < n; k++) {
                int j = (int)lst[l][k] * PITCH;
                float4 av = *(const float4*)&xt[j + rr*4];
                float4 bv = *(const float4*)&xt[j + cr*4];
                acc[l][0]  += av.x*bv.x; acc[l][1]  += av.x*bv.y;
                acc[l][2]  += av.x*bv.z; acc[l][3]  += av.x*bv.w;
                acc[l][4]  += av.y*bv.x; acc[l][5]  += av.y*bv.y;
                acc[l][6]  += av.y*bv.z; acc[l][7]  += av.y*bv.w;
                acc[l][8]  += av.z*bv.x; acc[l][9]  += av.z*bv.y;
                acc[l][10] += av.z*bv.z; acc[l][11] += av.z*bv.w;
                acc[l][12] += av.w*bv.x; acc[l][13] += av.w*bv.y;
                acc[l][14] += av.w*bv.z; acc[l][15] += av.w*bv.w;
            }
        }
    }
    __syncthreads();
    if (tid < NL) atomicAdd(&g_cnt[which][tid], gcnt[tid]);
    for (int k = tid; k < NL*CC; k += 256)
        atomicAdd(&g_S1[which][0][0] + k, (&s1[0][0])[k]);
    float* S2g = &g_S2[which][0][0];
    #pragma unroll
    for (int l = 0; l < NL; l++) {
        int b = l*CC*CC + (rr*4)*CC + cr*4;
        #pragma unroll
        for (int r = 0; r < 4; r++)
            #pragma unroll
            for (int c = 0; c < 4; c++)
                atomicAdd(&S2g[b + r*CC + c], acc[l][r*4 + c]);
    }
}

// ---------------- 64x64x64 in-block matmul, 256 threads ----------------
// C = A@B, or (nsform) C = 1.5 I - 0.5 A@B
__device__ __forceinline__ void mm64(float* __restrict__ C,
                                     const float* __restrict__ A,
                                     const float* __restrict__ B,
                                     int tid, int nsform) {
    int rr = tid >> 4, cr = tid & 15;
    float acc[4][4] = {};
    #pragma unroll 4
    for (int k = 0; k < 64; k += 4) {
        float4 a[4], b[4];
        #pragma unroll
        for (int r = 0; r < 4; r++) a[r] = *(const float4*)&A[(rr*4 + r)*64 + k];
        #pragma unroll
        for (int i = 0; i < 4; i++) b[i] = *(const float4*)&B[(k + i)*64 + cr*4];
        #pragma unroll
        for (int r = 0; r < 4; r++) {
            float4 ar = a[r];
            acc[r][0] += ar.x*b[0].x + ar.y*b[1].x + ar.z*b[2].x + ar.w*b[3].x;
            acc[r][1] += ar.x*b[0].y + ar.y*b[1].y + ar.z*b[2].y + ar.w*b[3].y;
            acc[r][2] += ar.x*b[0].z + ar.y*b[1].z + ar.z*b[2].z + ar.w*b[3].z;
            acc[r][3] += ar.x*b[0].w + ar.y*b[1].w + ar.z*b[2].w + ar.w*b[3].w;
        }
    }
    #pragma unroll
    for (int r = 0; r < 4; r++)
        #pragma unroll
        for (int c = 0; c < 4; c++) {
            float v = acc[r][c];
            if (nsform) v = ((rr*4 + r) == (cr*4 + c) ? 1.5f : 0.f) - 0.5f*v;
            C[(rr*4 + r)*64 + cr*4 + c] = v;
        }
}

// ============ Newton-Schulz: cov -> cov^{-1/2} (content) / cov^{1/2} (style) ============
__global__ __launch_bounds__(256, 1) void ns_kernel() {
    extern __shared__ float sm[];
    float *Yp = sm, *Zp = sm + 4096, *Wp = sm + 8192, *Vp = sm + 12288;
    int lab = blockIdx.x >> 1, which = blockIdx.x & 1;
    int tid = threadIdx.x;
    __shared__ float mu[CC], rowsum[CC], s_sh;

    unsigned int n = g_cnt[which][lab];
    float fn = (float)n;
    if (tid < CC) mu[tid] = g_S1[which][lab][tid] / fmaxf(fn, 1.f);
    __syncthreads();
    float div = (fn - 1.f == 0.f) ? 1e-5f : (fn - 1.f);
    for (int k = tid; k < 4096; k += 256) {
        int i = k >> 6, j = k & 63;
        float a = (g_S2[which][lab][k] - fn*mu[i]*mu[j]) / div;
        if (which == 0 && i == j) a += 1.f;
        Yp[k] = a;
    }
    __syncthreads();
    if (n <= 10u) {  // label invalid -> output never used; write identity
        for (int k = tid; k < 4096; k += 256)
            g_WC[which][lab][k] = ((k >> 6) == (k & 63)) ? 1.f : 0.f;
        if (tid < CC) g_mu[which][lab][tid] = mu[tid];
        return;
    }
    if (tid < CC) {
        float sr = 0.f;
        for (int j = 0; j < 64; j++) sr += fabsf(Yp[tid*64 + j]);
        rowsum[tid] = sr;
    }
    __syncthreads();
    if (tid == 0) {
        float m = 1e-10f;
        for (int i = 0; i < CC; i++) m = fmaxf(m, rowsum[i]);
        s_sh = m;
    }
    __syncthreads();
    float s = s_sh, inv_s = 1.f / s;
    for (int k = tid; k < 4096; k += 256) {
        Yp[k] *= inv_s;
        Zp[k] = ((k >> 6) == (k & 63)) ? 1.f : 0.f;
    }
    __syncthreads();
    for (int it = 0; it < NS_IT; it++) {
        mm64(Wp, Zp, Yp, tid, 1);     // W = 1.5I - 0.5 Z@Y
        __syncthreads();
        mm64(Vp, Yp, Wp, tid, 0);     // newY = Y@W
        __syncthreads();
        mm64(Yp, Wp, Zp, tid, 0);     // newZ = W@Z (old Y buffer now free)
        __syncthreads();
        float* t = Yp; Yp = Vp; Vp = Zp; Zp = t;   // Y<-newY, Z<-newZ
    }
    float fac = (which == 0) ? rsqrtf(s) : sqrtf(s);
    const float* src = (which == 0) ? Zp : Yp;
    for (int k = tid; k < 4096; k += 256) g_WC[which][lab][k] = src[k] * fac;
    if (tid < CC) g_mu[which][lab][tid] = mu[tid];
}

// ============ combine: T = Co@Wh, beta = mu_s - T mu_c, valid flag ============
__global__ __launch_bounds__(256, 1) void combine_kernel() {
    __shared__ float Co[4096], Wh[4096];
    int lab = blockIdx.x, tid = threadIdx.x;
    for (int k = tid; k < 4096; k += 256) {
        Co[k] = g_WC[1][lab][k];
        Wh[k] = g_WC[0][lab][k];
    }
    __syncthreads();
    mm64(g_T[lab], Co, Wh, tid, 0);
    __threadfence_block();
    __syncthreads();
    if (tid < CC) {
        float b = g_mu[1][lab][tid];
        const float* Tr = &g_T[lab][tid*64];
        #pragma unroll 8
        for (int q = 0; q < CC; q++) b -= Tr[q] * g_mu[0][lab][q];
        g_beta[lab][tid] = b;
    }
    if (tid == 0) {
        float nc = (float)g_cnt[0][lab], ns = (float)g_cnt[1][lab];
        g_valid[lab] = (nc > 10.f) && (ns > 10.f) && (nc < 100.f*ns) && (ns < 100.f*nc);
    }
}

// ================= apply: out = valid ? T x + beta : x =================
__global__ __launch_bounds__(256, 1)
void apply_kernel(const float* __restrict__ cf, const int* __restrict__ cs,
                  float* __restrict__ out) {
    extern __shared__ float sm[];
    float* Ts  = sm;                       // [NL][TSTRIDE] bank-padded
    float* bet = sm + NL*TSTRIDE;          // [NL][CC]
    __shared__ int val[NL];
    int tid = threadIdx.x;
    for (int k = tid; k < NL*CC*CC; k += 256) {
        int l = k >> 12, o = k & 4095;
        Ts[l*TSTRIDE + o] = (&g_T[0][0])[k];
    }
    for (int k = tid; k < NL*CC; k += 256) bet[k] = (&g_beta[0][0])[k];
    if (tid < NL) val[tid] = g_valid[tid];
    __syncthreads();

    for (int t = blockIdx.x; t < NATILE; t += gridDim.x) {
        int p = t*APT + tid;
        int lab = cs[p] & 7;
        float x[CC];
        #pragma unroll
        for (int c = 0; c < CC; c++) x[c] = cf[c*NPIX + p];
        if (!val[lab]) {
            #pragma unroll
            for (int c = 0; c < CC; c++) out[c*NPIX + p] = x[c];
            continue;
        }
        const float* T = Ts + lab*TSTRIDE;
        const float* bl = bet + lab*CC;
        for (int c0 = 0; c0 < CC; c0 += 4) {
            float a0 = 0.f, a1 = 0.f, a2 = 0.f, a3 = 0.f;
            #pragma unroll
            for (int q = 0; q < CC; q += 4) {
                float4 t0 = *(const float4*)&T[(c0+0)*64 + q];
                float4 t1 = *(const float4*)&T[(c0+1)*64 + q];
                float4 t2 = *(const float4*)&T[(c0+2)*64 + q];
                float4 t3 = *(const float4*)&T[(c0+3)*64 + q];
                a0 += t0.x*x[q] + t0.y*x[q+1] + t0.z*x[q+2] + t0.w*x[q+3];
                a1 += t1.x*x[q] + t1.y*x[q+1] + t1.z*x[q+2] + t1.w*x[q+3];
                a2 += t2.x*x[q] + t2.y*x[q+1] + t2.z*x[q+2] + t2.w*x[q+3];
                a3 += t3.x*x[q] + t3.y*x[q+1] + t3.z*x[q+2] + t3.w*x[q+3];
            }
            out[(c0+0)*NPIX + p] = a0 + bl[c0+0];
            out[(c0+1)*NPIX + p] = a1 + bl[c0+1];
            out[(c0+2)*NPIX + p] = a2 + bl[c0+2];
            out[(c0+3)*NPIX + p] = a3 + bl[c0+3];
        }
    }
}

extern "C" void kernel_launch(void* const* d_in, const int* in_sizes, int n_in,
                              void* d_out, int out_size) {
    const float* cf = (const float*)d_in[0];
    const float* sf = (const float*)d_in[1];
    const int*   cs = (const int*)d_in[2];
    const int*   ss = (const int*)d_in[3];
    float* out = (float*)d_out;

    int apply_smem = NL*TSTRIDE*4 + NL*CC*4;
    cudaFuncSetAttribute(ns_kernel, cudaFuncAttributeMaxDynamicSharedMemorySize, 65536);
    cudaFuncSetAttribute(apply_kernel, cudaFuncAttributeMaxDynamicSharedMemorySize, apply_smem);

    zero_kernel<<<64, 256>>>();
    stats_kernel<<<dim3(148, 2), 256>>>(cf, sf, cs, ss);
    ns_kernel<<<16, 256, 65536>>>();
    combine_kernel<<<NL, 256>>>();
    apply_kernel<<<296, 256, apply_smem>>>(cf, cs, out);
}